// round 16
// baseline (speedup 1.0000x reference)
#include <cuda_runtime.h>
#include <cuda_bf16.h>
#include <cuda_fp16.h>
#include <stdint.h>

#define NN 50000
#define NE 640000
#define D  128
#define TM 128          // rows per GEMM CTA
#define CHK 12544       // 98 * 128: chunk size for 4-way pipelining
#define SPLIT 25088     // 2 * CHK: fill phase split
#define NBLK 196        // node blocks (256 nodes each)

// Scratch (no allocations allowed)
__device__ __half         g_hA[NN * D];
__device__ __half         g_hB[NN * D];
__device__ __nv_bfloat16  g_xhi[NN * D];
__device__ __nv_bfloat16  g_xlo[NN * D];
__device__ __nv_bfloat16  g_whi[3 * D * D];
__device__ __nv_bfloat16  g_wlo[3 * D * D];
__device__ int   g_degi[NN];
__device__ float g_dis[NN];
__device__ int   g_off[NN + 1];
__device__ int   g_cur[NN];
__device__ int   g_rows[NE];
__device__ float g_norm[NE];
__device__ int   g_bsum[256];
__device__ int   g_is64;

__device__ __forceinline__ uint32_t pack_bf2(float a, float b) {
    __nv_bfloat162 t = __floats2bfloat162_rn(a, b);
    return *(uint32_t*)&t;
}

#define MMA_BF16(c, a, b) \
    asm volatile("mma.sync.aligned.m16n8k16.row.col.f32.bf16.bf16.f32 " \
        "{%0,%1,%2,%3}, {%4,%5,%6,%7}, {%8,%9}, {%0,%1,%2,%3};" \
        : "+f"((c)[0]), "+f"((c)[1]), "+f"((c)[2]), "+f"((c)[3]) \
        : "r"((a)[0]), "r"((a)[1]), "r"((a)[2]), "r"((a)[3]), \
          "r"((b)[0]), "r"((b)[1]))

// ---------------------------------------------------------------------------
__global__ void zero_deg_kernel(const void* ei) {
    int i = blockIdx.x * blockDim.x + threadIdx.x;
    if (i < NN) g_degi[i] = 0;
    if (i == 0) {
        const long long* p = (const long long*)ei;
        int ok = 1;
        #pragma unroll
        for (int k = 0; k < 8; k++) {
            long long v = p[k];
            if (v < 0 || v >= NN) ok = 0;
        }
        g_is64 = ok;
    }
}

// 2 edges per thread, independent atomics.
__global__ void deg_count_kernel(const void* ei) {
    int t = blockIdx.x * blockDim.x + threadIdx.x;
    int e0 = t * 2;
    if (e0 >= NE) return;
    int c0, c1 = -1;
    if (g_is64) {
        const long long* p = (const long long*)ei + NE + e0;
        c0 = (int)p[0];
        if (e0 + 1 < NE) c1 = (int)p[1];
    } else {
        const int* p = (const int*)ei + NE + e0;
        c0 = p[0];
        if (e0 + 1 < NE) c1 = p[1];
    }
    atomicAdd(&g_degi[c0], 1);
    if (c1 >= 0) atomicAdd(&g_degi[c1], 1);
}

// Per-block degree sums.
__global__ void scanA_kernel() {
    __shared__ int sh[256];
    int i = blockIdx.x * 256 + threadIdx.x;
    sh[threadIdx.x] = (i < NN) ? g_degi[i] : 0;
    __syncthreads();
    for (int o = 128; o > 0; o >>= 1) {
        if (threadIdx.x < o) sh[threadIdx.x] += sh[threadIdx.x + o];
        __syncthreads();
    }
    if (threadIdx.x == 0) g_bsum[blockIdx.x] = sh[0];
}

// Merged scan (warp-shuffle version): per-block base from bsum prefix, then
// local 256-element scan; writes offsets, cursors and dis.
__global__ void scanC_kernel() {
    __shared__ int warp_sums[8];
    __shared__ int base_sh;
    int b = blockIdx.x, t = threadIdx.x;
    int lane = t & 31, w = t >> 5;

    // base = sum of g_bsum[0..b)   (NBLK <= 256)
    int v = (t < b) ? g_bsum[t] : 0;
    #pragma unroll
    for (int o = 16; o > 0; o >>= 1) v += __shfl_down_sync(~0u, v, o);
    if (lane == 0) warp_sums[w] = v;
    __syncthreads();
    if (t == 0) {
        int s = 0;
        #pragma unroll
        for (int k = 0; k < 8; k++) s += warp_sums[k];
        base_sh = s;
    }
    __syncthreads();
    int base = base_sh;

    int i = b * 256 + t;
    int d = (i < NN) ? g_degi[i] : 0;
    int sc = d;
    #pragma unroll
    for (int o = 1; o < 32; o <<= 1) {
        int u = __shfl_up_sync(~0u, sc, o);
        if (lane >= o) sc += u;
    }
    __syncthreads();
    if (lane == 31) warp_sums[w] = sc;
    __syncthreads();
    int woff = 0;
    #pragma unroll
    for (int k = 0; k < 8; k++)
        if (k < w) woff += warp_sums[k];
    int incl = sc + woff;
    if (i < NN) {
        int off = base + incl - d;
        g_off[i] = off;
        g_cur[i] = off;
        g_dis[i] = rsqrtf((float)(d + 1));
    }
    if (b == NBLK - 1 && t == 255) g_off[NN] = base + incl;
}

// 2 edges per thread; only edges whose destination col is in [lo, hi).
// Separate rows/norm stores (proven fastest for the gather).
__global__ void fill_kernel(const void* ei, int lo, int hi) {
    int t = blockIdx.x * blockDim.x + threadIdx.x;
    int e0 = t * 2;
    if (e0 >= NE) return;
    int r0, c0, r1 = -1, c1 = -1;
    if (g_is64) {
        const long long* pr = (const long long*)ei + e0;
        const long long* pc = (const long long*)ei + NE + e0;
        r0 = (int)pr[0]; c0 = (int)pc[0];
        if (e0 + 1 < NE) { r1 = (int)pr[1]; c1 = (int)pc[1]; }
    } else {
        const int* pr = (const int*)ei + e0;
        const int* pc = (const int*)ei + NE + e0;
        r0 = pr[0]; c0 = pc[0];
        if (e0 + 1 < NE) { r1 = pr[1]; c1 = pc[1]; }
    }
    if (c0 >= lo && c0 < hi) {
        float nm = g_dis[r0] * g_dis[c0];
        int p0 = atomicAdd(&g_cur[c0], 1);
        g_rows[p0] = r0;
        g_norm[p0] = nm;
    }
    if (r1 >= 0 && c1 >= lo && c1 < hi) {
        float nm = g_dis[r1] * g_dis[c1];
        int p1 = atomicAdd(&g_cur[c1], 1);
        g_rows[p1] = r1;
        g_norm[p1] = nm;
    }
}

// ---------------------------------------------------------------------------
// W[k][n] fp32 -> W^T hi/lo bf16 at [l][n][k].
__global__ void conv_w_kernel(const float* __restrict__ W0,
                              const float* __restrict__ W1,
                              const float* __restrict__ W2) {
    int idx = blockIdx.x * blockDim.x + threadIdx.x;
    if (idx >= 3 * D * D) return;
    int l = idx / (D * D);
    int rem = idx - l * D * D;
    int k = rem / D;
    int n = rem % D;
    const float* W = (l == 0) ? W0 : (l == 1) ? W1 : W2;
    float v = W[k * D + n];
    __nv_bfloat16 hi = __float2bfloat16(v);
    float lo = v - __bfloat162float(hi);
    g_whi[l * D * D + n * D + k] = hi;
    g_wlo[l * D * D + n * D + k] = __float2bfloat16(lo);
}

// ---------------------------------------------------------------------------
// Split-bf16 tensor-core GEMM via mma.sync.m16n8k16 (identical inner loops).
#define ROWW 68
#define TILE_W (TM * ROWW * 4)
#define SM_TOTAL (4 * TILE_W)

__global__ __launch_bounds__(256, 1) void mma_kernel(const float* __restrict__ xsrc,
                                                     int from_x, int layer,
                                                     int row_base, int hbuf) {
    extern __shared__ char smem[];
    uint32_t* AsHi = (uint32_t*)smem;
    uint32_t* AsLo = AsHi + TM * ROWW;
    uint32_t* WsHi = AsLo + TM * ROWW;
    uint32_t* WsLo = WsHi + TM * ROWW;

    int tid  = threadIdx.x;
    int wid  = tid >> 5;
    int lane = tid & 31;
    int row0 = row_base + blockIdx.x * TM;
    const int n = NN;
    __half* hdst = hbuf ? g_hB : g_hA;

    const uint4* Whi = (const uint4*)(g_whi + (size_t)layer * D * D);
    const uint4* Wlo = (const uint4*)(g_wlo + (size_t)layer * D * D);
    const uint4 z4 = make_uint4(0, 0, 0, 0);

    if (from_x) {
        const float4* X4 = (const float4*)(xsrc + (size_t)row0 * D);
        #pragma unroll
        for (int it = 0; it < 8; it++) {
            int i = tid + it * 256;
            int row = i >> 4;
            int c   = i & 15;
            int so  = row * (ROWW / 4) + c;
            uint4 vh = z4, vl = z4;
            if (row0 + row < n) {
                float4 f0 = X4[i * 2];
                float4 f1 = X4[i * 2 + 1];
                float h0 = __bfloat162float(__float2bfloat16(f0.x));
                float h1 = __bfloat162float(__float2bfloat16(f0.y));
                float h2 = __bfloat162float(__float2bfloat16(f0.z));
                float h3 = __bfloat162float(__float2bfloat16(f0.w));
                float h4 = __bfloat162float(__float2bfloat16(f1.x));
                float h5 = __bfloat162float(__float2bfloat16(f1.y));
                float h6 = __bfloat162float(__float2bfloat16(f1.z));
                float h7 = __bfloat162float(__float2bfloat16(f1.w));
                vh = make_uint4(pack_bf2(f0.x, f0.y), pack_bf2(f0.z, f0.w),
                                pack_bf2(f1.x, f1.y), pack_bf2(f1.z, f1.w));
                vl = make_uint4(pack_bf2(f0.x - h0, f0.y - h1),
                                pack_bf2(f0.z - h2, f0.w - h3),
                                pack_bf2(f1.x - h4, f1.y - h5),
                                pack_bf2(f1.z - h6, f1.w - h7));
            }
            ((uint4*)AsHi)[so] = vh;
            ((uint4*)AsLo)[so] = vl;
            ((uint4*)WsHi)[so] = Whi[i];
            ((uint4*)WsLo)[so] = Wlo[i];
        }
    } else {
        const uint4* Ahi = (const uint4*)(g_xhi + (size_t)row0 * D);
        const uint4* Alo = (const uint4*)(g_xlo + (size_t)row0 * D);
        #pragma unroll
        for (int it = 0; it < 8; it++) {
            int i = tid + it * 256;
            int row = i >> 4;
            int c   = i & 15;
            int so  = row * (ROWW / 4) + c;
            bool ok = (row0 + row < n);
            ((uint4*)AsHi)[so] = ok ? Ahi[i] : z4;
            ((uint4*)AsLo)[so] = ok ? Alo[i] : z4;
            ((uint4*)WsHi)[so] = Whi[i];
            ((uint4*)WsLo)[so] = Wlo[i];
        }
    }
    __syncthreads();

    int wm = wid >> 1;
    int wn = wid & 1;
    int g  = lane >> 2;
    int tg = lane & 3;

    float c[2][8][4];
    #pragma unroll
    for (int mt = 0; mt < 2; mt++)
        #pragma unroll
        for (int nt = 0; nt < 8; nt++)
            #pragma unroll
            for (int q = 0; q < 4; q++) c[mt][nt][q] = 0.f;

    #pragma unroll
    for (int pass = 0; pass < 3; pass++) {
        const uint32_t* As = (pass == 1) ? AsLo : AsHi;
        const uint32_t* Ws = (pass == 2) ? WsLo : WsHi;
        #pragma unroll
        for (int ks = 0; ks < 8; ks++) {
            uint32_t a[2][4];
            #pragma unroll
            for (int mt = 0; mt < 2; mt++) {
                int r = wm * 32 + mt * 16 + g;
                const uint32_t* p0 = As + r * ROWW + ks * 8 + tg;
                const uint32_t* p1 = As + (r + 8) * ROWW + ks * 8 + tg;
                a[mt][0] = p0[0];
                a[mt][1] = p1[0];
                a[mt][2] = p0[4];
                a[mt][3] = p1[4];
            }
            uint32_t b[8][2];
            #pragma unroll
            for (int nt = 0; nt < 8; nt++) {
                int ncol = wn * 64 + nt * 8 + g;
                const uint32_t* p = Ws + ncol * ROWW + ks * 8 + tg;
                b[nt][0] = p[0];
                b[nt][1] = p[4];
            }
            #pragma unroll
            for (int mt = 0; mt < 2; mt++)
                #pragma unroll
                for (int nt = 0; nt < 8; nt++)
                    MMA_BF16(c[mt][nt], a[mt], b[nt]);
        }
    }

    #pragma unroll
    for (int mt = 0; mt < 2; mt++) {
        int r = row0 + wm * 32 + mt * 16 + g;
        #pragma unroll
        for (int nt = 0; nt < 8; nt++) {
            int col = wn * 64 + nt * 8 + tg * 2;
            if (r < n)
                *(__half2*)&hdst[(size_t)r * D + col] =
                    __floats2half2_rn(c[mt][nt][0], c[mt][nt][1]);
            if (r + 8 < n)
                *(__half2*)&hdst[(size_t)(r + 8) * D + col] =
                    __floats2half2_rn(c[mt][nt][2], c[mt][nt][3]);
        }
    }
}

// ---------------------------------------------------------------------------
__device__ __forceinline__ float4 ld_h4(const uint2* h4, size_t idx) {
    uint2 raw = h4[idx];
    float2 a = __half22float2(*(__half2*)&raw.x);
    float2 b = __half22float2(*(__half2*)&raw.y);
    return make_float4(a.x, a.y, b.x, b.y);
}

__global__ void gather_kernel(const float* __restrict__ b,
                              float* __restrict__ out_ptr, int final_layer,
                              int node_base, int node_end, int hbuf) {
    unsigned gid = blockIdx.x * blockDim.x + threadIdx.x;
    int node = node_base + (int)(gid >> 5);
    if (node >= node_end) return;
    int lane = threadIdx.x & 31;

    const uint2* h4 = (const uint2*)(hbuf ? g_hB : g_hA);

    float di = g_dis[node];
    float d2 = di * di;
    float4 bb = ((const float4*)b)[lane];
    float4 hs = ld_h4(h4, (size_t)node * 32 + lane);
    float4 acc;
    acc.x = fmaf(hs.x, d2, bb.x);
    acc.y = fmaf(hs.y, d2, bb.y);
    acc.z = fmaf(hs.z, d2, bb.z);
    acc.w = fmaf(hs.w, d2, bb.w);

    int s = g_off[node];
    int e = g_off[node + 1];
    int j = s;
    for (; j + 3 < e; j += 4) {
        int   r0 = g_rows[j],     r1 = g_rows[j + 1];
        int   r2 = g_rows[j + 2], r3 = g_rows[j + 3];
        float n0 = g_norm[j],     n1 = g_norm[j + 1];
        float n2 = g_norm[j + 2], n3 = g_norm[j + 3];
        float4 v0 = ld_h4(h4, (size_t)r0 * 32 + lane);
        float4 v1 = ld_h4(h4, (size_t)r1 * 32 + lane);
        float4 v2 = ld_h4(h4, (size_t)r2 * 32 + lane);
        float4 v3 = ld_h4(h4, (size_t)r3 * 32 + lane);
        acc.x = fmaf(v0.x, n0, acc.x); acc.y = fmaf(v0.y, n0, acc.y);
        acc.z = fmaf(v0.z, n0, acc.z); acc.w = fmaf(v0.w, n0, acc.w);
        acc.x = fmaf(v1.x, n1, acc.x); acc.y = fmaf(v1.y, n1, acc.y);
        acc.z = fmaf(v1.z, n1, acc.z); acc.w = fmaf(v1.w, n1, acc.w);
        acc.x = fmaf(v2.x, n2, acc.x); acc.y = fmaf(v2.y, n2, acc.y);
        acc.z = fmaf(v2.z, n2, acc.z); acc.w = fmaf(v2.w, n2, acc.w);
        acc.x = fmaf(v3.x, n3, acc.x); acc.y = fmaf(v3.y, n3, acc.y);
        acc.z = fmaf(v3.z, n3, acc.z); acc.w = fmaf(v3.w, n3, acc.w);
    }
    for (; j < e; j++) {
        int   r  = g_rows[j];
        float nm = g_norm[j];
        float4 v = ld_h4(h4, (size_t)r * 32 + lane);
        acc.x = fmaf(v.x, nm, acc.x); acc.y = fmaf(v.y, nm, acc.y);
        acc.z = fmaf(v.z, nm, acc.z); acc.w = fmaf(v.w, nm, acc.w);
    }

    acc.x = fmaxf(acc.x, 0.f); acc.y = fmaxf(acc.y, 0.f);
    acc.z = fmaxf(acc.z, 0.f); acc.w = fmaxf(acc.w, 0.f);

    if (final_layer) {
        ((float4*)out_ptr)[(size_t)node * 32 + lane] = acc;
    } else {
        float hx = __bfloat162float(__float2bfloat16(acc.x));
        float hy = __bfloat162float(__float2bfloat16(acc.y));
        float hz = __bfloat162float(__float2bfloat16(acc.z));
        float hw = __bfloat162float(__float2bfloat16(acc.w));
        uint2 hi = make_uint2(pack_bf2(acc.x, acc.y), pack_bf2(acc.z, acc.w));
        uint2 lo = make_uint2(pack_bf2(acc.x - hx, acc.y - hy),
                              pack_bf2(acc.z - hz, acc.w - hw));
        ((uint2*)g_xhi)[(size_t)node * 32 + lane] = hi;
        ((uint2*)g_xlo)[(size_t)node * 32 + lane] = lo;
    }
}

// ---------------------------------------------------------------------------
extern "C" void kernel_launch(void* const* d_in, const int* in_sizes, int n_in,
                              void* d_out, int out_size) {
    const float* x  = (const float*)d_in[0];
    const void*  ei = d_in[1];
    const float* W[3] = {(const float*)d_in[2], (const float*)d_in[4],
                         (const float*)d_in[6]};
    const float* b[3] = {(const float*)d_in[3], (const float*)d_in[5],
                         (const float*)d_in[7]};
    float* out = (float*)d_out;

    static bool inited = false;
    static cudaStream_t s2, s3;
    static cudaEvent_t evFork, evPrepA, evPrepB;
    static cudaEvent_t evG[2][4], evJoin[2];
    if (!inited) {
        cudaFuncSetAttribute(mma_kernel,
                             cudaFuncAttributeMaxDynamicSharedMemorySize, SM_TOTAL);
        cudaStreamCreateWithFlags(&s2, cudaStreamNonBlocking);
        cudaStreamCreateWithFlags(&s3, cudaStreamNonBlocking);
        cudaEventCreateWithFlags(&evFork, cudaEventDisableTiming);
        cudaEventCreateWithFlags(&evPrepA, cudaEventDisableTiming);
        cudaEventCreateWithFlags(&evPrepB, cudaEventDisableTiming);
        for (int l = 0; l < 2; l++) {
            for (int c = 0; c < 4; c++)
                cudaEventCreateWithFlags(&evG[l][c], cudaEventDisableTiming);
            cudaEventCreateWithFlags(&evJoin[l], cudaEventDisableTiming);
        }
        inited = true;
    }

    const int edge2Blocks = (NE / 2 + 255) / 256;      // 1250
    const int mmaFull     = (NN + TM - 1) / TM;        // 391
    const int gAll        = (NN * 32 + 255) / 256;     // 6250
    const int convWBlocks = (3 * D * D + 255) / 256;

    // chunk bounds (node space, multiples of 128)
    const int cb[5] = {0, CHK, 2 * CHK, 3 * CHK, NN};

    // Fork: CSR prep on s2; fill split in two phases by destination column.
    cudaEventRecord(evFork, 0);
    cudaStreamWaitEvent(s2, evFork, 0);
    zero_deg_kernel<<<NBLK, 256, 0, s2>>>(ei);
    deg_count_kernel<<<edge2Blocks, 256, 0, s2>>>(ei);
    scanA_kernel<<<NBLK, 256, 0, s2>>>();
    scanC_kernel<<<NBLK, 256, 0, s2>>>();
    fill_kernel<<<edge2Blocks, 256, 0, s2>>>(ei, 0, SPLIT);
    cudaEventRecord(evPrepA, s2);
    fill_kernel<<<edge2Blocks, 256, 0, s2>>>(ei, SPLIT, NN);
    cudaEventRecord(evPrepB, s2);

    // Main stream: conv_w + full mma0 -> hA (independent of prep).
    conv_w_kernel<<<convWBlocks, 256>>>(W[0], W[1], W[2]);
    mma_kernel<<<mmaFull, 256, SM_TOTAL>>>(x, 1, 0, 0, 0);

    // Layer boundaries 0->1 and 1->2: 4-way chunked pipeline.
    // Main: 4 gather chunks; s3: 4 mma chunks, each gated on its gather.
    for (int l = 0; l < 2; l++) {
        int rbuf = l & 1;          // gather_l reads hA (l=0) / hB (l=1)
        int wbuf = 1 - rbuf;       // mma_{l+1} writes the other buffer
        if (l == 0) {
            cudaStreamWaitEvent(0, evPrepA, 0);
        } else {
            cudaStreamWaitEvent(0, evJoin[0], 0);
        }
        for (int c = 0; c < 4; c++) {
            if (l == 0 && c == 2) cudaStreamWaitEvent(0, evPrepB, 0);
            int nb = cb[c], ne = cb[c + 1];
            int gBlocks = ((ne - nb) * 32 + 255) / 256;
            gather_kernel<<<gBlocks, 256>>>(b[l], out, 0, nb, ne, rbuf);
            cudaEventRecord(evG[l][c], 0);
        }
        for (int c = 0; c < 4; c++) {
            cudaStreamWaitEvent(s3, evG[l][c], 0);
            int nb = cb[c], ne = cb[c + 1];
            int mBlocks = (ne - nb + TM - 1) / TM;
            mma_kernel<<<mBlocks, 256, SM_TOTAL, s3>>>(x, 0, l + 1, nb, wbuf);
        }
        cudaEventRecord(evJoin[l], s3);
    }

    // Final gather (full range, reads hA (layer 2 wrote buf 0), ReLU out).
    cudaStreamWaitEvent(0, evJoin[1], 0);
    gather_kernel<<<gAll, 256>>>(b[2], out, 1, 0, NN, 0);
}

// round 17
// speedup vs baseline: 1.1018x; 1.1018x over previous
#include <cuda_runtime.h>
#include <cuda_bf16.h>
#include <cuda_fp16.h>
#include <stdint.h>

#define NN 50000
#define NE 640000
#define D  128
#define TM 128          // rows per GEMM CTA
#define SPLIT 25088     // 196 * 128: node split for pipelining
#define NBLK 196        // node blocks (256 nodes each)

// Scratch (no allocations allowed)
__device__ __half         g_hA[NN * D];
__device__ __half         g_hB[NN * D];
__device__ __nv_bfloat16  g_xhi[NN * D];
__device__ __nv_bfloat16  g_xlo[NN * D];
__device__ __nv_bfloat16  g_whi[3 * D * D];
__device__ __nv_bfloat16  g_wlo[3 * D * D];
__device__ int   g_degi[NN];
__device__ float g_dis[NN];
__device__ int   g_off[NN + 1];
__device__ int   g_cur[NN];
__device__ int   g_rows[NE];
__device__ float g_norm[NE];
__device__ int   g_bsum[256];
__device__ int   g_is64;

__device__ __forceinline__ uint32_t pack_bf2(float a, float b) {
    __nv_bfloat162 t = __floats2bfloat162_rn(a, b);
    return *(uint32_t*)&t;
}

#define MMA_BF16(c, a, b) \
    asm volatile("mma.sync.aligned.m16n8k16.row.col.f32.bf16.bf16.f32 " \
        "{%0,%1,%2,%3}, {%4,%5,%6,%7}, {%8,%9}, {%0,%1,%2,%3};" \
        : "+f"((c)[0]), "+f"((c)[1]), "+f"((c)[2]), "+f"((c)[3]) \
        : "r"((a)[0]), "r"((a)[1]), "r"((a)[2]), "r"((a)[3]), \
          "r"((b)[0]), "r"((b)[1]))

// ---------------------------------------------------------------------------
__global__ void zero_deg_kernel(const void* ei) {
    int i = blockIdx.x * blockDim.x + threadIdx.x;
    if (i < NN) g_degi[i] = 0;
    if (i == 0) {
        const long long* p = (const long long*)ei;
        int ok = 1;
        #pragma unroll
        for (int k = 0; k < 8; k++) {
            long long v = p[k];
            if (v < 0 || v >= NN) ok = 0;
        }
        g_is64 = ok;
    }
}

// 2 edges per thread, independent atomics.
__global__ void deg_count_kernel(const void* ei) {
    int t = blockIdx.x * blockDim.x + threadIdx.x;
    int e0 = t * 2;
    if (e0 >= NE) return;
    int c0, c1 = -1;
    if (g_is64) {
        const long long* p = (const long long*)ei + NE + e0;
        c0 = (int)p[0];
        if (e0 + 1 < NE) c1 = (int)p[1];
    } else {
        const int* p = (const int*)ei + NE + e0;
        c0 = p[0];
        if (e0 + 1 < NE) c1 = p[1];
    }
    atomicAdd(&g_degi[c0], 1);
    if (c1 >= 0) atomicAdd(&g_degi[c1], 1);
}

// Per-block degree sums.
__global__ void scanA_kernel() {
    __shared__ int sh[256];
    int i = blockIdx.x * 256 + threadIdx.x;
    sh[threadIdx.x] = (i < NN) ? g_degi[i] : 0;
    __syncthreads();
    for (int o = 128; o > 0; o >>= 1) {
        if (threadIdx.x < o) sh[threadIdx.x] += sh[threadIdx.x + o];
        __syncthreads();
    }
    if (threadIdx.x == 0) g_bsum[blockIdx.x] = sh[0];
}

// Merged scan (warp-shuffle): per-block base from bsum prefix, then local scan.
__global__ void scanC_kernel() {
    __shared__ int warp_sums[8];
    __shared__ int base_sh;
    int b = blockIdx.x, t = threadIdx.x;
    int lane = t & 31, w = t >> 5;

    int v = (t < b) ? g_bsum[t] : 0;
    #pragma unroll
    for (int o = 16; o > 0; o >>= 1) v += __shfl_down_sync(~0u, v, o);
    if (lane == 0) warp_sums[w] = v;
    __syncthreads();
    if (t == 0) {
        int s = 0;
        #pragma unroll
        for (int k = 0; k < 8; k++) s += warp_sums[k];
        base_sh = s;
    }
    __syncthreads();
    int base = base_sh;

    int i = b * 256 + t;
    int d = (i < NN) ? g_degi[i] : 0;
    int sc = d;
    #pragma unroll
    for (int o = 1; o < 32; o <<= 1) {
        int u = __shfl_up_sync(~0u, sc, o);
        if (lane >= o) sc += u;
    }
    __syncthreads();
    if (lane == 31) warp_sums[w] = sc;
    __syncthreads();
    int woff = 0;
    #pragma unroll
    for (int k = 0; k < 8; k++)
        if (k < w) woff += warp_sums[k];
    int incl = sc + woff;
    if (i < NN) {
        int off = base + incl - d;
        g_off[i] = off;
        g_cur[i] = off;
        g_dis[i] = rsqrtf((float)(d + 1));
    }
    if (b == NBLK - 1 && t == 255) g_off[NN] = base + incl;
}

// 2 edges per thread; only edges whose destination col is in [lo, hi).
// Disjoint col ranges touch disjoint cursors/CSR segments -> race-free
// when two instances run concurrently on different streams.
__global__ void fill_kernel(const void* ei, int lo, int hi) {
    int t = blockIdx.x * blockDim.x + threadIdx.x;
    int e0 = t * 2;
    if (e0 >= NE) return;
    int r0, c0, r1 = -1, c1 = -1;
    if (g_is64) {
        const long long* pr = (const long long*)ei + e0;
        const long long* pc = (const long long*)ei + NE + e0;
        r0 = (int)pr[0]; c0 = (int)pc[0];
        if (e0 + 1 < NE) { r1 = (int)pr[1]; c1 = (int)pc[1]; }
    } else {
        const int* pr = (const int*)ei + e0;
        const int* pc = (const int*)ei + NE + e0;
        r0 = pr[0]; c0 = pc[0];
        if (e0 + 1 < NE) { r1 = pr[1]; c1 = pc[1]; }
    }
    if (c0 >= lo && c0 < hi) {
        float nm = g_dis[r0] * g_dis[c0];
        int p0 = atomicAdd(&g_cur[c0], 1);
        g_rows[p0] = r0;
        g_norm[p0] = nm;
    }
    if (r1 >= 0 && c1 >= lo && c1 < hi) {
        float nm = g_dis[r1] * g_dis[c1];
        int p1 = atomicAdd(&g_cur[c1], 1);
        g_rows[p1] = r1;
        g_norm[p1] = nm;
    }
}

// ---------------------------------------------------------------------------
// W[k][n] fp32 -> W^T hi/lo bf16 at [l][n][k].
__global__ void conv_w_kernel(const float* __restrict__ W0,
                              const float* __restrict__ W1,
                              const float* __restrict__ W2) {
    int idx = blockIdx.x * blockDim.x + threadIdx.x;
    if (idx >= 3 * D * D) return;
    int l = idx / (D * D);
    int rem = idx - l * D * D;
    int k = rem / D;
    int n = rem % D;
    const float* W = (l == 0) ? W0 : (l == 1) ? W1 : W2;
    float v = W[k * D + n];
    __nv_bfloat16 hi = __float2bfloat16(v);
    float lo = v - __bfloat162float(hi);
    g_whi[l * D * D + n * D + k] = hi;
    g_wlo[l * D * D + n * D + k] = __float2bfloat16(lo);
}

// ---------------------------------------------------------------------------
// Split-bf16 tensor-core GEMM via mma.sync.m16n8k16 (identical inner loops).
#define ROWW 68
#define TILE_W (TM * ROWW * 4)
#define SM_TOTAL (4 * TILE_W)

__global__ __launch_bounds__(256, 1) void mma_kernel(const float* __restrict__ xsrc,
                                                     int from_x, int layer,
                                                     int row_base, int hbuf) {
    extern __shared__ char smem[];
    uint32_t* AsHi = (uint32_t*)smem;
    uint32_t* AsLo = AsHi + TM * ROWW;
    uint32_t* WsHi = AsLo + TM * ROWW;
    uint32_t* WsLo = WsHi + TM * ROWW;

    int tid  = threadIdx.x;
    int wid  = tid >> 5;
    int lane = tid & 31;
    int row0 = row_base + blockIdx.x * TM;
    const int n = NN;
    __half* hdst = hbuf ? g_hB : g_hA;

    const uint4* Whi = (const uint4*)(g_whi + (size_t)layer * D * D);
    const uint4* Wlo = (const uint4*)(g_wlo + (size_t)layer * D * D);
    const uint4 z4 = make_uint4(0, 0, 0, 0);

    if (from_x) {
        const float4* X4 = (const float4*)(xsrc + (size_t)row0 * D);
        #pragma unroll
        for (int it = 0; it < 8; it++) {
            int i = tid + it * 256;
            int row = i >> 4;
            int c   = i & 15;
            int so  = row * (ROWW / 4) + c;
            uint4 vh = z4, vl = z4;
            if (row0 + row < n) {
                float4 f0 = X4[i * 2];
                float4 f1 = X4[i * 2 + 1];
                float h0 = __bfloat162float(__float2bfloat16(f0.x));
                float h1 = __bfloat162float(__float2bfloat16(f0.y));
                float h2 = __bfloat162float(__float2bfloat16(f0.z));
                float h3 = __bfloat162float(__float2bfloat16(f0.w));
                float h4 = __bfloat162float(__float2bfloat16(f1.x));
                float h5 = __bfloat162float(__float2bfloat16(f1.y));
                float h6 = __bfloat162float(__float2bfloat16(f1.z));
                float h7 = __bfloat162float(__float2bfloat16(f1.w));
                vh = make_uint4(pack_bf2(f0.x, f0.y), pack_bf2(f0.z, f0.w),
                                pack_bf2(f1.x, f1.y), pack_bf2(f1.z, f1.w));
                vl = make_uint4(pack_bf2(f0.x - h0, f0.y - h1),
                                pack_bf2(f0.z - h2, f0.w - h3),
                                pack_bf2(f1.x - h4, f1.y - h5),
                                pack_bf2(f1.z - h6, f1.w - h7));
            }
            ((uint4*)AsHi)[so] = vh;
            ((uint4*)AsLo)[so] = vl;
            ((uint4*)WsHi)[so] = Whi[i];
            ((uint4*)WsLo)[so] = Wlo[i];
        }
    } else {
        const uint4* Ahi = (const uint4*)(g_xhi + (size_t)row0 * D);
        const uint4* Alo = (const uint4*)(g_xlo + (size_t)row0 * D);
        #pragma unroll
        for (int it = 0; it < 8; it++) {
            int i = tid + it * 256;
            int row = i >> 4;
            int c   = i & 15;
            int so  = row * (ROWW / 4) + c;
            bool ok = (row0 + row < n);
            ((uint4*)AsHi)[so] = ok ? Ahi[i] : z4;
            ((uint4*)AsLo)[so] = ok ? Alo[i] : z4;
            ((uint4*)WsHi)[so] = Whi[i];
            ((uint4*)WsLo)[so] = Wlo[i];
        }
    }
    __syncthreads();

    int wm = wid >> 1;
    int wn = wid & 1;
    int g  = lane >> 2;
    int tg = lane & 3;

    float c[2][8][4];
    #pragma unroll
    for (int mt = 0; mt < 2; mt++)
        #pragma unroll
        for (int nt = 0; nt < 8; nt++)
            #pragma unroll
            for (int q = 0; q < 4; q++) c[mt][nt][q] = 0.f;

    #pragma unroll
    for (int pass = 0; pass < 3; pass++) {
        const uint32_t* As = (pass == 1) ? AsLo : AsHi;
        const uint32_t* Ws = (pass == 2) ? WsLo : WsHi;
        #pragma unroll
        for (int ks = 0; ks < 8; ks++) {
            uint32_t a[2][4];
            #pragma unroll
            for (int mt = 0; mt < 2; mt++) {
                int r = wm * 32 + mt * 16 + g;
                const uint32_t* p0 = As + r * ROWW + ks * 8 + tg;
                const uint32_t* p1 = As + (r + 8) * ROWW + ks * 8 + tg;
                a[mt][0] = p0[0];
                a[mt][1] = p1[0];
                a[mt][2] = p0[4];
                a[mt][3] = p1[4];
            }
            uint32_t b[8][2];
            #pragma unroll
            for (int nt = 0; nt < 8; nt++) {
                int ncol = wn * 64 + nt * 8 + g;
                const uint32_t* p = Ws + ncol * ROWW + ks * 8 + tg;
                b[nt][0] = p[0];
                b[nt][1] = p[4];
            }
            #pragma unroll
            for (int mt = 0; mt < 2; mt++)
                #pragma unroll
                for (int nt = 0; nt < 8; nt++)
                    MMA_BF16(c[mt][nt], a[mt], b[nt]);
        }
    }

    #pragma unroll
    for (int mt = 0; mt < 2; mt++) {
        int r = row0 + wm * 32 + mt * 16 + g;
        #pragma unroll
        for (int nt = 0; nt < 8; nt++) {
            int col = wn * 64 + nt * 8 + tg * 2;
            if (r < n)
                *(__half2*)&hdst[(size_t)r * D + col] =
                    __floats2half2_rn(c[mt][nt][0], c[mt][nt][1]);
            if (r + 8 < n)
                *(__half2*)&hdst[(size_t)(r + 8) * D + col] =
                    __floats2half2_rn(c[mt][nt][2], c[mt][nt][3]);
        }
    }
}

// ---------------------------------------------------------------------------
__device__ __forceinline__ float4 ld_h4(const uint2* h4, size_t idx) {
    uint2 raw = h4[idx];
    float2 a = __half22float2(*(__half2*)&raw.x);
    float2 b = __half22float2(*(__half2*)&raw.y);
    return make_float4(a.x, a.y, b.x, b.y);
}

__global__ void gather_kernel(const float* __restrict__ b,
                              float* __restrict__ out_ptr, int final_layer,
                              int node_base, int node_end, int hbuf) {
    unsigned gid = blockIdx.x * blockDim.x + threadIdx.x;
    int node = node_base + (int)(gid >> 5);
    if (node >= node_end) return;
    int lane = threadIdx.x & 31;

    const uint2* h4 = (const uint2*)(hbuf ? g_hB : g_hA);

    float di = g_dis[node];
    float d2 = di * di;
    float4 bb = ((const float4*)b)[lane];
    float4 hs = ld_h4(h4, (size_t)node * 32 + lane);
    float4 acc;
    acc.x = fmaf(hs.x, d2, bb.x);
    acc.y = fmaf(hs.y, d2, bb.y);
    acc.z = fmaf(hs.z, d2, bb.z);
    acc.w = fmaf(hs.w, d2, bb.w);

    int s = g_off[node];
    int e = g_off[node + 1];
    int j = s;
    for (; j + 3 < e; j += 4) {
        int   r0 = g_rows[j],     r1 = g_rows[j + 1];
        int   r2 = g_rows[j + 2], r3 = g_rows[j + 3];
        float n0 = g_norm[j],     n1 = g_norm[j + 1];
        float n2 = g_norm[j + 2], n3 = g_norm[j + 3];
        float4 v0 = ld_h4(h4, (size_t)r0 * 32 + lane);
        float4 v1 = ld_h4(h4, (size_t)r1 * 32 + lane);
        float4 v2 = ld_h4(h4, (size_t)r2 * 32 + lane);
        float4 v3 = ld_h4(h4, (size_t)r3 * 32 + lane);
        acc.x = fmaf(v0.x, n0, acc.x); acc.y = fmaf(v0.y, n0, acc.y);
        acc.z = fmaf(v0.z, n0, acc.z); acc.w = fmaf(v0.w, n0, acc.w);
        acc.x = fmaf(v1.x, n1, acc.x); acc.y = fmaf(v1.y, n1, acc.y);
        acc.z = fmaf(v1.z, n1, acc.z); acc.w = fmaf(v1.w, n1, acc.w);
        acc.x = fmaf(v2.x, n2, acc.x); acc.y = fmaf(v2.y, n2, acc.y);
        acc.z = fmaf(v2.z, n2, acc.z); acc.w = fmaf(v2.w, n2, acc.w);
        acc.x = fmaf(v3.x, n3, acc.x); acc.y = fmaf(v3.y, n3, acc.y);
        acc.z = fmaf(v3.z, n3, acc.z); acc.w = fmaf(v3.w, n3, acc.w);
    }
    for (; j < e; j++) {
        int   r  = g_rows[j];
        float nm = g_norm[j];
        float4 v = ld_h4(h4, (size_t)r * 32 + lane);
        acc.x = fmaf(v.x, nm, acc.x); acc.y = fmaf(v.y, nm, acc.y);
        acc.z = fmaf(v.z, nm, acc.z); acc.w = fmaf(v.w, nm, acc.w);
    }

    acc.x = fmaxf(acc.x, 0.f); acc.y = fmaxf(acc.y, 0.f);
    acc.z = fmaxf(acc.z, 0.f); acc.w = fmaxf(acc.w, 0.f);

    if (final_layer) {
        ((float4*)out_ptr)[(size_t)node * 32 + lane] = acc;
    } else {
        float hx = __bfloat162float(__float2bfloat16(acc.x));
        float hy = __bfloat162float(__float2bfloat16(acc.y));
        float hz = __bfloat162float(__float2bfloat16(acc.z));
        float hw = __bfloat162float(__float2bfloat16(acc.w));
        uint2 hi = make_uint2(pack_bf2(acc.x, acc.y), pack_bf2(acc.z, acc.w));
        uint2 lo = make_uint2(pack_bf2(acc.x - hx, acc.y - hy),
                              pack_bf2(acc.z - hz, acc.w - hw));
        ((uint2*)g_xhi)[(size_t)node * 32 + lane] = hi;
        ((uint2*)g_xlo)[(size_t)node * 32 + lane] = lo;
    }
}

// ---------------------------------------------------------------------------
extern "C" void kernel_launch(void* const* d_in, const int* in_sizes, int n_in,
                              void* d_out, int out_size) {
    const float* x  = (const float*)d_in[0];
    const void*  ei = d_in[1];
    const float* W[3] = {(const float*)d_in[2], (const float*)d_in[4],
                         (const float*)d_in[6]};
    const float* b[3] = {(const float*)d_in[3], (const float*)d_in[5],
                         (const float*)d_in[7]};
    float* out = (float*)d_out;

    static bool inited = false;
    static cudaStream_t s2, s3, s4;
    static cudaEvent_t evFork, evScan, evFillA, evFillB;
    static cudaEvent_t evG0a, evM1a, evG1a, evM2a;
    if (!inited) {
        cudaFuncSetAttribute(mma_kernel,
                             cudaFuncAttributeMaxDynamicSharedMemorySize, SM_TOTAL);
        cudaStreamCreateWithFlags(&s2, cudaStreamNonBlocking);
        cudaStreamCreateWithFlags(&s3, cudaStreamNonBlocking);
        cudaStreamCreateWithFlags(&s4, cudaStreamNonBlocking);
        cudaEventCreateWithFlags(&evFork, cudaEventDisableTiming);
        cudaEventCreateWithFlags(&evScan, cudaEventDisableTiming);
        cudaEventCreateWithFlags(&evFillA, cudaEventDisableTiming);
        cudaEventCreateWithFlags(&evFillB, cudaEventDisableTiming);
        cudaEventCreateWithFlags(&evG0a, cudaEventDisableTiming);
        cudaEventCreateWithFlags(&evM1a, cudaEventDisableTiming);
        cudaEventCreateWithFlags(&evG1a, cudaEventDisableTiming);
        cudaEventCreateWithFlags(&evM2a, cudaEventDisableTiming);
        inited = true;
    }

    const int edge2Blocks = (NE / 2 + 255) / 256;      // 1250
    const int mmaFull     = (NN + TM - 1) / TM;        // 391
    const int mmaH0       = SPLIT / TM;                // 196
    const int mmaH1       = (NN - SPLIT + TM - 1) / TM;// 195
    const int gAll        = (NN * 32 + 255) / 256;     // 6250
    const int gH0         = SPLIT * 32 / 256;          // 3136
    const int gH1         = (NN - SPLIT) * 32 / 256;   // 3114
    const int convWBlocks = (3 * D * D + 255) / 256;

    // Fork: CSR prep on s2; two fill phases run CONCURRENTLY on s2 and s4.
    cudaEventRecord(evFork, 0);
    cudaStreamWaitEvent(s2, evFork, 0);
    zero_deg_kernel<<<NBLK, 256, 0, s2>>>(ei);
    deg_count_kernel<<<edge2Blocks, 256, 0, s2>>>(ei);
    scanA_kernel<<<NBLK, 256, 0, s2>>>();
    scanC_kernel<<<NBLK, 256, 0, s2>>>();
    cudaEventRecord(evScan, s2);
    cudaStreamWaitEvent(s4, evScan, 0);
    fill_kernel<<<edge2Blocks, 256, 0, s2>>>(ei, 0, SPLIT);
    cudaEventRecord(evFillA, s2);
    fill_kernel<<<edge2Blocks, 256, 0, s4>>>(ei, SPLIT, NN);
    cudaEventRecord(evFillB, s4);

    // Main stream: conv_w + full mma0 -> hA (independent of prep)
    conv_w_kernel<<<convWBlocks, 256>>>(W[0], W[1], W[2]);
    mma_kernel<<<mmaFull, 256, SM_TOTAL>>>(x, 1, 0, 0, 0);
    cudaStreamWaitEvent(0, evFillA, 0);
    cudaStreamWaitEvent(0, evFillB, 0);

    // Layer 0: gather reads hA; mma1(H0)->hB overlaps gather0(H1) on s3.
    gather_kernel<<<gH0, 256>>>(b[0], out, 0, 0, SPLIT, 0);
    cudaEventRecord(evG0a, 0);
    gather_kernel<<<gH1, 256>>>(b[0], out, 0, SPLIT, NN, 0);

    cudaStreamWaitEvent(s3, evG0a, 0);
    mma_kernel<<<mmaH0, 256, SM_TOTAL, s3>>>(x, 0, 1, 0, 1);
    cudaEventRecord(evM1a, s3);

    mma_kernel<<<mmaH1, 256, SM_TOTAL>>>(x, 0, 1, SPLIT, 1);
    cudaStreamWaitEvent(0, evM1a, 0);

    // Layer 1: gather reads hB; mma2(H0)->hA overlaps gather1(H1) on s3.
    gather_kernel<<<gH0, 256>>>(b[1], out, 0, 0, SPLIT, 1);
    cudaEventRecord(evG1a, 0);
    gather_kernel<<<gH1, 256>>>(b[1], out, 0, SPLIT, NN, 1);

    cudaStreamWaitEvent(s3, evG1a, 0);
    mma_kernel<<<mmaH0, 256, SM_TOTAL, s3>>>(x, 0, 2, 0, 0);
    cudaEventRecord(evM2a, s3);

    mma_kernel<<<mmaH1, 256, SM_TOTAL>>>(x, 0, 2, SPLIT, 0);
    cudaStreamWaitEvent(0, evM2a, 0);

    // Final gather (full range, reads hA, writes out with ReLU).
    gather_kernel<<<gAll, 256>>>(b[2], out, 1, 0, NN, 0);
}